// round 5
// baseline (speedup 1.0000x reference)
#include <cuda_runtime.h>

// reblurWithKernel: spatially-varying 33x33 blur, per-4x4-block kernels.
// out[c,h,w] = sum_{u,v} in[clamp(h+u-16),clamp(w+v-16)] * K[u*33+v, h/4, w/4]

#define KW     33
#define BLK    4
#define PAD    16
#define HH     512
#define WW     512
#define HB     128
#define WBNUM  128
#define TWB    8                 // wb blocks per CTA
#define THB    4                 // hb blocks per CTA
#define PROWS  (THB*BLK + 2*PAD) // 48
#define PCOLS  (TWB*BLK + 2*PAD) // 64
#define PSTR   68                // padded smem row stride (floats) to dodge bank patterns
#define NTHREADS 96

__global__ __launch_bounds__(NTHREADS)
void reblur_kernel(const float* __restrict__ img,
                   const float* __restrict__ ker,
                   float* __restrict__ out)
{
    __shared__ __align__(16) float sp[3][PROWS][PSTR];

    const int tid = threadIdx.x;
    const int WB0 = blockIdx.x * TWB;
    const int HB0 = blockIdx.y * THB;

    // ---- cooperative patch load (edge-clamped), 3 channels ----
    const int row0 = HB0 * BLK - PAD;
    const int col0 = WB0 * BLK - PAD;
    for (int idx = tid; idx < 3 * PROWS * PCOLS; idx += NTHREADS) {
        int c   = idx / (PROWS * PCOLS);
        int rem = idx - c * (PROWS * PCOLS);
        int r   = rem / PCOLS;
        int cc  = rem - r * PCOLS;
        int ir  = min(max(row0 + r, 0), HH - 1);
        int ic  = min(max(col0 + cc, 0), WW - 1);
        sp[c][r][cc] = img[c * (HH * WW) + ir * WW + ic];
    }
    __syncthreads();

    // ---- work mapping: warp = channel, lane = block within 8x4 tile ----
    const int c    = tid >> 5;       // 0..2
    const int lane = tid & 31;
    const int wbL  = lane & 7;       // 0..7
    const int hbL  = lane >> 3;      // 0..3
    const int hb4  = hbL * BLK;
    const int wb4  = wbL * BLK;

    float acc[4][4];
#pragma unroll
    for (int i = 0; i < 4; i++)
#pragma unroll
        for (int j = 0; j < 4; j++)
            acc[i][j] = 0.0f;

    // Kernels element offset for tap t: t*HB*WBNUM + hb*WBNUM + wb
    const float* kbase = ker + (HB0 + hbL) * WBNUM + (WB0 + wbL);

    for (int u = 0; u < KW; u++) {
        // load one kernel row (33 taps) into registers; coalesced across lanes
        float kr[KW];
        const float* kp = kbase + (u * KW) * (HB * WBNUM);
#pragma unroll
        for (int v = 0; v < KW; v++)
            kr[v] = __ldg(kp + v * (HB * WBNUM));

#pragma unroll
        for (int oi = 0; oi < 4; oi++) {
            // sliding row buffer: 36 floats via 9x LDS.128
            float rbuf[36];
            const float4* rp =
                reinterpret_cast<const float4*>(&sp[c][hb4 + u + oi][wb4]);
#pragma unroll
            for (int i = 0; i < 9; i++) {
                float4 t = rp[i];
                rbuf[4 * i + 0] = t.x;
                rbuf[4 * i + 1] = t.y;
                rbuf[4 * i + 2] = t.z;
                rbuf[4 * i + 3] = t.w;
            }
#pragma unroll
            for (int v = 0; v < KW; v++) {
                const float k = kr[v];
                acc[oi][0] += k * rbuf[v + 0];
                acc[oi][1] += k * rbuf[v + 1];
                acc[oi][2] += k * rbuf[v + 2];
                acc[oi][3] += k * rbuf[v + 3];
            }
        }
    }

    // ---- store 4x4 outputs as four STG.128 ----
    float* ob = out + c * (HH * WW) + ((HB0 + hbL) * BLK) * WW + (WB0 + wbL) * BLK;
#pragma unroll
    for (int oi = 0; oi < 4; oi++) {
        float4 val = make_float4(acc[oi][0], acc[oi][1], acc[oi][2], acc[oi][3]);
        *reinterpret_cast<float4*>(ob + oi * WW) = val;
    }
}

extern "C" void kernel_launch(void* const* d_in, const int* in_sizes, int n_in,
                              void* d_out, int out_size)
{
    const float* img = (const float*)d_in[0];  // (1,3,512,512) fp32
    const float* ker = (const float*)d_in[1];  // (1,1089,128,128) fp32
    float* out = (float*)d_out;                // (1,3,512,512) fp32
    (void)in_sizes; (void)n_in; (void)out_size;

    dim3 grid(WBNUM / TWB, HB / THB);  // (16, 32)
    reblur_kernel<<<grid, NTHREADS>>>(img, ker, out);
}

// round 6
// speedup vs baseline: 1.0651x; 1.0651x over previous
#include <cuda_runtime.h>

// reblurWithKernel: spatially-varying 33x33 blur, per-4x4-block kernels.
// out[c,h,w] = sum_{u,v} in[clamp(h+u-16),clamp(w+v-16)] * K[u*33+v, h/4, w/4]
//
// R6: u-parity split. Each (block,channel) unit is computed by TWO threads:
// half=0 sums even kernel rows, half=1 odd rows. 192 threads (6 warps) per CTA
// doubles resident warps (occupancy was the binding constraint at 14.8%).
// Pipe traffic (FMA / LDS / kernel LDG) per unit is unchanged; halves load
// disjoint u rows. Final combine via smem (patch buffer reused after sync).

#define KW     33
#define BLK    4
#define PAD    16
#define HH     512
#define WW     512
#define HB     128
#define WBNUM  128
#define TWB    8                 // wb blocks per CTA
#define THB    4                 // hb blocks per CTA
#define PROWS  (THB*BLK + 2*PAD) // 48
#define PCOLS  (TWB*BLK + 2*PAD) // 64
#define PSTR   68                // padded smem row stride (floats)
#define NTHREADS 192

__global__ __launch_bounds__(NTHREADS, 4)
void reblur_kernel(const float* __restrict__ img,
                   const float* __restrict__ ker,
                   float* __restrict__ out)
{
    __shared__ __align__(16) float sp[3][PROWS][PSTR];

    const int tid = threadIdx.x;
    const int WB0 = blockIdx.x * TWB;
    const int HB0 = blockIdx.y * THB;

    // ---- cooperative patch load (edge-clamped), 3 channels ----
    const int row0 = HB0 * BLK - PAD;
    const int col0 = WB0 * BLK - PAD;
    for (int idx = tid; idx < 3 * PROWS * PCOLS; idx += NTHREADS) {
        int c   = idx / (PROWS * PCOLS);
        int rem = idx - c * (PROWS * PCOLS);
        int r   = rem / PCOLS;
        int cc  = rem - r * PCOLS;
        int ir  = min(max(row0 + r, 0), HH - 1);
        int ic  = min(max(col0 + cc, 0), WW - 1);
        sp[c][r][cc] = img[c * (HH * WW) + ir * WW + ic];
    }
    __syncthreads();

    // ---- work mapping ----
    // tid 0..95   : half=0 (even kernel rows u), warps 0-2 = channels 0-2
    // tid 96..191 : half=1 (odd  kernel rows u), warps 3-5 = channels 0-2
    const int half = (tid >= 96) ? 1 : 0;
    const int base = tid - half * 96;     // 0..95
    const int c    = base >> 5;           // 0..2
    const int lane = base & 31;
    const int wbL  = lane & 7;            // 0..7
    const int hbL  = lane >> 3;           // 0..3
    const int hb4  = hbL * BLK;
    const int wb4  = wbL * BLK;

    float acc[4][4];
#pragma unroll
    for (int i = 0; i < 4; i++)
#pragma unroll
        for (int j = 0; j < 4; j++)
            acc[i][j] = 0.0f;

    // Kernels element offset for tap t: t*HB*WBNUM + hb*WBNUM + wb
    const float* kbase = ker + (HB0 + hbL) * WBNUM + (WB0 + wbL);

#pragma unroll 1
    for (int u = half; u < KW; u += 2) {
        // load one kernel row (33 taps) into registers; coalesced across lanes
        float kr[KW];
        const float* kp = kbase + (u * KW) * (HB * WBNUM);
#pragma unroll
        for (int v = 0; v < KW; v++)
            kr[v] = __ldg(kp + v * (HB * WBNUM));

#pragma unroll
        for (int oi = 0; oi < 4; oi++) {
            // sliding row buffer: 36 floats via 9x LDS.128
            float rbuf[36];
            const float4* rp =
                reinterpret_cast<const float4*>(&sp[c][hb4 + u + oi][wb4]);
#pragma unroll
            for (int i = 0; i < 9; i++) {
                float4 t = rp[i];
                rbuf[4 * i + 0] = t.x;
                rbuf[4 * i + 1] = t.y;
                rbuf[4 * i + 2] = t.z;
                rbuf[4 * i + 3] = t.w;
            }
#pragma unroll
            for (int v = 0; v < KW; v++) {
                const float k = kr[v];
                acc[oi][0] += k * rbuf[v + 0];
                acc[oi][1] += k * rbuf[v + 1];
                acc[oi][2] += k * rbuf[v + 2];
                acc[oi][3] += k * rbuf[v + 3];
            }
        }
    }

    // ---- combine halves via smem (reuse patch buffer) and store ----
    __syncthreads();   // everyone done reading sp
    float* red = &sp[0][0][0];   // 96 units x 16 floats = 6144 B << 39 KB
    if (half == 1) {
        float* dst = red + base * 16;
#pragma unroll
        for (int oi = 0; oi < 4; oi++) {
            float4 v = make_float4(acc[oi][0], acc[oi][1], acc[oi][2], acc[oi][3]);
            *reinterpret_cast<float4*>(dst + oi * 4) = v;
        }
    }
    __syncthreads();
    if (half == 0) {
        const float* src = red + base * 16;
        float* ob = out + c * (HH * WW)
                  + ((HB0 + hbL) * BLK) * WW + (WB0 + wbL) * BLK;
#pragma unroll
        for (int oi = 0; oi < 4; oi++) {
            float4 o = *reinterpret_cast<const float4*>(src + oi * 4);
            float4 val = make_float4(acc[oi][0] + o.x, acc[oi][1] + o.y,
                                     acc[oi][2] + o.z, acc[oi][3] + o.w);
            *reinterpret_cast<float4*>(ob + oi * WW) = val;
        }
    }
}

extern "C" void kernel_launch(void* const* d_in, const int* in_sizes, int n_in,
                              void* d_out, int out_size)
{
    const float* img = (const float*)d_in[0];  // (1,3,512,512) fp32
    const float* ker = (const float*)d_in[1];  // (1,1089,128,128) fp32
    float* out = (float*)d_out;                // (1,3,512,512) fp32
    (void)in_sizes; (void)n_in; (void)out_size;

    dim3 grid(WBNUM / TWB, HB / THB);  // (16, 32)
    reblur_kernel<<<grid, NTHREADS>>>(img, ker, out);
}

// round 7
// speedup vs baseline: 1.0960x; 1.0290x over previous
#include <cuda_runtime.h>

// reblurWithKernel: spatially-varying 33x33 blur, per-4x4-block kernels.
// out[c,h,w] = sum_{u,v} in[clamp(h+u-16),clamp(w+v-16)] * K[u*33+v, h/4, w/4]
//
// R7: CTA tile = 32 wb x 1 hb so each warp's 32 lanes read 32 CONSECUTIVE wb
// of the kernel tensor -> every kernel LDG is one contiguous 128B wavefront
// (was 4 scattered sectors = 4 wavefronts, and kernel LDGs were ~half of all
// L1 traffic). 384 threads = 3 channels x 4 u-quarters (u = q mod 4) for
// 24 warps/SM at 2 CTAs/SM. Patch 3x36x164 fp32 = 69KB dynamic smem.
// Quarters combine through smem (patch buffer reused), q=0 stores.

#define KW     33
#define BLK    4
#define PAD    16
#define HH     512
#define WW     512
#define HB     128
#define WBNUM  128
#define TWB    32                 // wb blocks per CTA
#define PROWS  (BLK + 2*PAD)      // 36
#define PCOLS  (TWB*BLK + 2*PAD)  // 160
#define PSTR   164                // row stride (floats), 656B = 16B aligned
#define NTHREADS 384
#define SMEM_FLOATS (3 * PROWS * PSTR)
#define SMEM_BYTES  (SMEM_FLOATS * 4)

__global__ __launch_bounds__(NTHREADS, 2)
void reblur_kernel(const float* __restrict__ img,
                   const float* __restrict__ ker,
                   float* __restrict__ out)
{
    extern __shared__ __align__(16) float sm[];
    // sp(c, r, cc) = sm[c*PROWS*PSTR + r*PSTR + cc]

    const int tid = threadIdx.x;
    const int WB0 = blockIdx.x * TWB;   // block-column base
    const int HB0 = blockIdx.y;         // single block-row

    // ---- cooperative patch load (edge-clamped), 3 channels ----
    const int row0 = HB0 * BLK - PAD;
    const int col0 = WB0 * BLK - PAD;
    for (int idx = tid; idx < 3 * PROWS * PCOLS; idx += NTHREADS) {
        int c   = idx / (PROWS * PCOLS);
        int rem = idx - c * (PROWS * PCOLS);
        int r   = rem / PCOLS;
        int cc  = rem - r * PCOLS;
        int ir  = min(max(row0 + r, 0), HH - 1);
        int ic  = min(max(col0 + cc, 0), WW - 1);
        sm[c * (PROWS * PSTR) + r * PSTR + cc] = img[c * (HH * WW) + ir * WW + ic];
    }
    __syncthreads();

    // ---- work mapping: 12 warps = 3 channels x 4 u-quarters ----
    const int w    = tid >> 5;    // warp 0..11
    const int lane = tid & 31;    // wb block within tile
    const int c    = w >> 2;      // 0..2  channel
    const int q    = w & 3;       // 0..3  u-quarter (u = q mod 4)
    const int wb4  = lane * BLK;  // patch column base for this block

    const float* spc = sm + c * (PROWS * PSTR);

    float acc[4][4];
#pragma unroll
    for (int i = 0; i < 4; i++)
#pragma unroll
        for (int j = 0; j < 4; j++)
            acc[i][j] = 0.0f;

    // Kernels element offset for tap t: t*HB*WBNUM + hb*WBNUM + wb
    // 32 lanes -> 32 consecutive wb -> 128B contiguous per LDG.
    const float* kbase = ker + HB0 * WBNUM + (WB0 + lane);

#pragma unroll 1
    for (int u = q; u < KW; u += 4) {
        // one kernel row (33 taps) into registers; 1 wavefront per load
        float kr[KW];
        const float* kp = kbase + (u * KW) * (HB * WBNUM);
#pragma unroll
        for (int v = 0; v < KW; v++)
            kr[v] = __ldg(kp + v * (HB * WBNUM));

#pragma unroll
        for (int oi = 0; oi < 4; oi++) {
            // sliding row buffer: 36 floats via 9x LDS.128 (contiguous warp-wide)
            float rbuf[36];
            const float4* rp =
                reinterpret_cast<const float4*>(spc + (u + oi) * PSTR + wb4);
#pragma unroll
            for (int i = 0; i < 9; i++) {
                float4 t = rp[i];
                rbuf[4 * i + 0] = t.x;
                rbuf[4 * i + 1] = t.y;
                rbuf[4 * i + 2] = t.z;
                rbuf[4 * i + 3] = t.w;
            }
#pragma unroll
            for (int v = 0; v < KW; v++) {
                const float k = kr[v];
                acc[oi][0] += k * rbuf[v + 0];
                acc[oi][1] += k * rbuf[v + 1];
                acc[oi][2] += k * rbuf[v + 2];
                acc[oi][3] += k * rbuf[v + 3];
            }
        }
    }

    // ---- combine the 4 u-quarters via smem (reuse patch buffer) ----
    __syncthreads();               // everyone done reading the patch
    const int unit = c * 32 + lane;        // 0..95
    if (q != 0) {
        float* dst = sm + ((q - 1) * 96 + unit) * 16;
#pragma unroll
        for (int oi = 0; oi < 4; oi++) {
            float4 v = make_float4(acc[oi][0], acc[oi][1], acc[oi][2], acc[oi][3]);
            *reinterpret_cast<float4*>(dst + oi * 4) = v;
        }
    }
    __syncthreads();
    if (q == 0) {
#pragma unroll
        for (int p = 0; p < 3; p++) {
            const float* src = sm + (p * 96 + unit) * 16;
#pragma unroll
            for (int oi = 0; oi < 4; oi++) {
                float4 o = *reinterpret_cast<const float4*>(src + oi * 4);
                acc[oi][0] += o.x; acc[oi][1] += o.y;
                acc[oi][2] += o.z; acc[oi][3] += o.w;
            }
        }
        // coalesced store: 32 lanes x 16B = 512B contiguous per row
        float* ob = out + c * (HH * WW) + (HB0 * BLK) * WW + (WB0 + lane) * BLK;
#pragma unroll
        for (int oi = 0; oi < 4; oi++) {
            float4 val = make_float4(acc[oi][0], acc[oi][1], acc[oi][2], acc[oi][3]);
            *reinterpret_cast<float4*>(ob + oi * WW) = val;
        }
    }
}

extern "C" void kernel_launch(void* const* d_in, const int* in_sizes, int n_in,
                              void* d_out, int out_size)
{
    const float* img = (const float*)d_in[0];  // (1,3,512,512) fp32
    const float* ker = (const float*)d_in[1];  // (1,1089,128,128) fp32
    float* out = (float*)d_out;                // (1,3,512,512) fp32
    (void)in_sizes; (void)n_in; (void)out_size;

    static bool attr_done = false;
    // idempotent, not an allocation; safe under graph capture
    cudaFuncSetAttribute(reblur_kernel,
                         cudaFuncAttributeMaxDynamicSharedMemorySize, SMEM_BYTES);
    (void)attr_done;

    dim3 grid(WBNUM / TWB, HB);  // (4, 128) = 512 CTAs
    reblur_kernel<<<grid, NTHREADS, SMEM_BYTES>>>(img, ker, out);
}